// round 13
// baseline (speedup 1.0000x reference)
#include <cuda_runtime.h>
#include <cuda_fp16.h>
#include <cstdint>

// NTN: out[n,k] = relu( cos(x1@W1[k], x2@W2[k]) + [x1,x2]@V[k] + b[k] )
// R13: R12 with prep_p2 grid bug fixed (was 512 sub-blocks -> OOB reads at
// n up to 65535; correct is 128 n-blocks x 2 k-halves = 256 sub-blocks).
// Main kernel identical to validated R11.

#define NN 32768
#define DD 128
#define KK 32
#define EPSN 1e-8f

// ---------------- global scratch ----------------
__device__ uint4 gXfrag[2][2048][8][32];   // [mat][rowtile16][ds][lane] fp16 A-frags
__device__ uint4 gWh[32][2][2048];         // [k][chunk][granule] fp16 W
__device__ float gP2[(size_t)NN * KK];     // part2 + bias

// ---------------- helpers ----------------
static __device__ __forceinline__ uint32_t s2u(const void* p) {
    uint32_t a;
    asm("{ .reg .u64 t; cvta.to.shared.u64 t, %1; cvt.u32.u64 %0, t; }"
        : "=r"(a) : "l"(p));
    return a;
}
static __device__ __forceinline__ uint32_t packh2(float a, float b) {
    __half2 h = __floats2half2_rn(a, b);
    return *reinterpret_cast<uint32_t*>(&h);
}

#define LDSM4T(R, addr)                                                         \
    asm volatile("ldmatrix.sync.aligned.m8n8.x4.trans.shared.b16 {%0,%1,%2,%3},[%4];" \
                 : "=r"((R)[0]), "=r"((R)[1]), "=r"((R)[2]), "=r"((R)[3])       \
                 : "r"(addr))

#define HMMA(C, A, B0, B1)                                                      \
    asm volatile("mma.sync.aligned.m16n8k16.row.col.f32.f16.f16.f32 "           \
                 "{%0,%1,%2,%3},{%4,%5,%6,%7},{%8,%9},{%0,%1,%2,%3};"           \
                 : "+f"((C)[0]), "+f"((C)[1]), "+f"((C)[2]), "+f"((C)[3])       \
                 : "r"((A).x), "r"((A).y), "r"((A).z), "r"((A).w),              \
                   "r"(B0), "r"(B1))

static __device__ __forceinline__ void cp16(uint32_t dst, const void* src) {
    asm volatile("cp.async.cg.shared.global [%0], [%1], 16;"
                 :: "r"(dst), "l"(src) : "memory");
}
static __device__ __forceinline__ void cp_commit() {
    asm volatile("cp.async.commit_group;" ::: "memory");
}
template <int N>
static __device__ __forceinline__ void cp_wait() {
    asm volatile("cp.async.wait_group %0;" :: "n"(N) : "memory");
}

// ---------------- fused prep kernel ----------------
// blocks [0,512):     X -> fp16 A-fragments
// blocks [512,1024):  W -> fp16 granules
// blocks [1024,1280): part2+bias (128 n-blocks x 2 k-halves)
__global__ __launch_bounds__(256) void prep_all(const float* __restrict__ x1,
                                                const float* __restrict__ x2,
                                                const float* __restrict__ W1,
                                                const float* __restrict__ W2,
                                                const float* __restrict__ Vg,
                                                const float* __restrict__ bg) {
    const int bid = blockIdx.x;
    const int tid = threadIdx.x;

    if (bid < 512) {
        // ---- prep_x ----
        int wid  = (bid * 256 + tid) >> 5;   // 0..4095
        int lane = tid & 31;
        int m  = wid >> 11;
        int rt = wid & 2047;
        const float* x = m ? x2 : x1;
        const float* p0 = x + (size_t)(rt * 16 + (lane >> 2)) * DD;
        const float* p1 = p0 + 8 * DD;
        const int c0 = (lane & 3) * 2;
        #pragma unroll
        for (int ds = 0; ds < 8; ds++) {
            int c = ds * 16 + c0;
            float2 v0 = *(const float2*)(p0 + c);
            float2 v1 = *(const float2*)(p1 + c);
            float2 v2 = *(const float2*)(p0 + c + 8);
            float2 v3 = *(const float2*)(p1 + c + 8);
            gXfrag[m][rt][ds][lane] = make_uint4(packh2(v0.x, v0.y), packh2(v1.x, v1.y),
                                                 packh2(v2.x, v2.y), packh2(v3.x, v3.y));
        }
    } else if (bid < 1024) {
        // ---- prep_w : t bits e8:0-2, d:3-9, mat:10, ch:11, k:12-16 ----
        int t   = (bid - 512) * 256 + tid;   // 0..131071
        int e8  = t & 7;
        int d   = (t >> 3) & 127;
        int mat = (t >> 10) & 1;
        int ch  = (t >> 11) & 1;
        int k   = t >> 12;
        const float* w = (mat ? W2 : W1) + (size_t)k * DD * DD + (size_t)d * DD
                       + ch * 64 + e8 * 8;
        uint32_t hh[4];
        #pragma unroll
        for (int j = 0; j < 4; j++) hh[j] = packh2(w[2 * j], w[2 * j + 1]);
        gWh[k][ch][mat * 1024 + d * 8 + e8] = make_uint4(hh[0], hh[1], hh[2], hh[3]);
    } else {
        // ---- prep_p2 (k-half split): sub = nblk*2 + kh, sub in [0,256) ----
        __shared__ float Vs[16 * 256];
        __shared__ float bs[16];
        const int sub = bid - 1024;          // 0..255
        const int kh  = sub & 1;
        const int n   = (sub >> 1) * 256 + tid;   // 0..32767
        const int kb  = kh * 16;
        for (int i = tid; i < 16 * 256; i += 256) Vs[i] = Vg[(kb * 256) + i];
        if (tid < 16) bs[tid] = bg[kb + tid];
        __syncthreads();
        float acc[16];
        #pragma unroll
        for (int k = 0; k < 16; k++) acc[k] = bs[k];
        const float4* xa = (const float4*)(x1 + (size_t)n * DD);
        const float4* xb = (const float4*)(x2 + (size_t)n * DD);
        #pragma unroll 4
        for (int f = 0; f < 32; f++) {
            float4 xv = xa[f];
            #pragma unroll
            for (int k = 0; k < 16; k++) {
                float4 vv = *(const float4*)(&Vs[k * 256 + f * 4]);
                acc[k] = fmaf(xv.x, vv.x, fmaf(xv.y, vv.y,
                         fmaf(xv.z, vv.z, fmaf(xv.w, vv.w, acc[k]))));
            }
        }
        #pragma unroll 4
        for (int f = 0; f < 32; f++) {
            float4 xv = xb[f];
            #pragma unroll
            for (int k = 0; k < 16; k++) {
                float4 vv = *(const float4*)(&Vs[k * 256 + 128 + f * 4]);
                acc[k] = fmaf(xv.x, vv.x, fmaf(xv.y, vv.y,
                         fmaf(xv.z, vv.z, fmaf(xv.w, vv.w, acc[k]))));
            }
        }
        #pragma unroll
        for (int k = 0; k < 16; k++) gP2[(size_t)n * KK + kb + k] = acc[k];
    }
}

// ---------------- main kernel (identical to R11) ----------------
#define WROWB 144                    // 128B data (64 fp16 cols) + 16B pad
#define WPL   (128 * WROWB)          // 18432 per mat tile
#define CHUNKB (2 * WPL)             // 36864 per chunk (2 mats)
#define OFF_STG (2 * CHUNKB)         // 73728 (both chunks resident)
#define SMEM_MAIN (OFF_STG + 8 * 4096)  // 106496

__global__ __launch_bounds__(256, 2)
void ntn_main(float* __restrict__ out) {
    extern __shared__ char smem[];
    const uint32_t sb = s2u(smem);
    const int tid  = threadIdx.x;
    const int lane = tid & 31;
    const int w    = tid >> 5;     // warp 0..7: rows 32*w .. +31 (of 256)
    const int k     = blockIdx.y;
    const int rbase = blockIdx.x * 256;
    const int rtb   = blockIdx.x * 16 + w * 2;

    // ---- cp.async BOTH chunks upfront (disjoint buffers) ----
    #pragma unroll
    for (int ch = 0; ch < 2; ch++) {
        #pragma unroll
        for (int i = 0; i < 8; i++) {
            int idx = tid + 256 * i;            // 0..2047
            int mp  = idx >> 10;
            int d   = (idx >> 3) & 127;
            int e8  = idx & 7;
            cp16(sb + ch * CHUNKB + mp * WPL + d * WROWB + e8 * 16,
                 &gWh[k][ch][idx]);
        }
        cp_commit();
    }

    const int arow  = (lane & 7) + ((lane >> 3) & 1) * 8;
    const int half8 = lane >> 4;
    const uint32_t boff = (uint32_t)(arow * WROWB + half8 * 16);
    char* stg = smem + OFF_STG + w * 4096 + lane * 8;

    // ---- A register double-buffer: prefetch step (g=0, ds=0) ----
    uint4 a[2][2];
    a[0][0] = gXfrag[0][rtb][0][lane];
    a[0][1] = gXfrag[0][rtb + 1][0][lane];

    float dv[4]  = {0.f, 0.f, 0.f, 0.f};
    float n1v[4] = {0.f, 0.f, 0.f, 0.f};
    float n2v[4] = {0.f, 0.f, 0.f, 0.f};

    cp_wait<1>();
    __syncthreads();

    #pragma unroll 1
    for (int c = 0; c < 2; c++) {
        if (c == 1) { cp_wait<0>(); __syncthreads(); }
        const uint32_t cbuf = sb + c * CHUNKB;

        #pragma unroll 1
        for (int g = 0; g < 2; g++) {
            float cc[2][8][4];
            #pragma unroll
            for (int mt = 0; mt < 2; mt++)
                #pragma unroll
                for (int nt = 0; nt < 8; nt++)
                    #pragma unroll
                    for (int q = 0; q < 4; q++) cc[mt][nt][q] = 0.f;

            #pragma unroll
            for (int ds = 0; ds < 8; ds++) {
                const int cur = ds & 1, nxt = cur ^ 1;
                const int gn = (ds < 7) ? g : (g ^ 1);
                const int dn = (ds < 7) ? (ds + 1) : 0;
                a[nxt][0] = gXfrag[gn][rtb][dn][lane];
                a[nxt][1] = gXfrag[gn][rtb + 1][dn][lane];

                uint32_t bb[4][4];
                const uint32_t tb = cbuf + g * WPL + (uint32_t)(ds * 16 * WROWB) + boff;
                LDSM4T(bb[0], tb);
                LDSM4T(bb[1], tb + 32);
                LDSM4T(bb[2], tb + 64);
                LDSM4T(bb[3], tb + 96);

                #pragma unroll
                for (int cb = 0; cb < 4; cb++) {
                    HMMA(cc[0][cb * 2],     a[cur][0], bb[cb][0], bb[cb][1]);
                    HMMA(cc[1][cb * 2],     a[cur][1], bb[cb][0], bb[cb][1]);
                    HMMA(cc[0][cb * 2 + 1], a[cur][0], bb[cb][2], bb[cb][3]);
                    HMMA(cc[1][cb * 2 + 1], a[cur][1], bb[cb][2], bb[cb][3]);
                }
            }

            if (g == 0) {
                #pragma unroll
                for (int mt = 0; mt < 2; mt++)
                    #pragma unroll
                    for (int nt = 0; nt < 8; nt++) {
                        uint2 pv;
                        pv.x = packh2(cc[mt][nt][0], cc[mt][nt][1]);
                        pv.y = packh2(cc[mt][nt][2], cc[mt][nt][3]);
                        *(uint2*)(stg + (mt * 8 + nt) * 256) = pv;
                    }
            } else {
                #pragma unroll
                for (int mt = 0; mt < 2; mt++)
                    #pragma unroll
                    for (int nt = 0; nt < 8; nt++) {
                        uint2 pv = *(const uint2*)(stg + (mt * 8 + nt) * 256);
                        float2 f0 = __half22float2(*reinterpret_cast<__half2*>(&pv.x));
                        float2 f1 = __half22float2(*reinterpret_cast<__half2*>(&pv.y));
                        const int s0 = mt * 2;
                        float b0 = cc[mt][nt][0], b1 = cc[mt][nt][1];
                        float b2 = cc[mt][nt][2], b3 = cc[mt][nt][3];
                        dv[s0]      = fmaf(f0.x, b0, fmaf(f0.y, b1, dv[s0]));
                        n1v[s0]     = fmaf(f0.x, f0.x, fmaf(f0.y, f0.y, n1v[s0]));
                        n2v[s0]     = fmaf(b0, b0, fmaf(b1, b1, n2v[s0]));
                        dv[s0 + 1]  = fmaf(f1.x, b2, fmaf(f1.y, b3, dv[s0 + 1]));
                        n1v[s0 + 1] = fmaf(f1.x, f1.x, fmaf(f1.y, f1.y, n1v[s0 + 1]));
                        n2v[s0 + 1] = fmaf(b2, b2, fmaf(b3, b3, n2v[s0 + 1]));
                    }
            }
        }
    }

    // ---- lane reduce (4 lanes share a row); rows are warp-exclusive ----
    #pragma unroll
    for (int s = 0; s < 4; s++) {
        #pragma unroll
        for (int off = 1; off <= 2; off <<= 1) {
            dv[s]  += __shfl_xor_sync(0xffffffffu, dv[s],  off);
            n1v[s] += __shfl_xor_sync(0xffffffffu, n1v[s], off);
            n2v[s] += __shfl_xor_sync(0xffffffffu, n2v[s], off);
        }
    }
    if ((lane & 3) == 0) {
        #pragma unroll
        for (int s = 0; s < 4; s++) {
            const int row = w * 32 + (s >> 1) * 16 + (s & 1) * 8 + (lane >> 2);
            float s1 = fmaxf(sqrtf(n1v[s]), EPSN);
            float s2 = fmaxf(sqrtf(n2v[s]), EPSN);
            float v  = dv[s] / (s1 * s2) + gP2[(size_t)(rbase + row) * KK + k];
            out[(size_t)(rbase + row) * KK + k] = fmaxf(v, 0.f);
        }
    }
}

extern "C" void kernel_launch(void* const* d_in, const int* in_sizes, int n_in,
                              void* d_out, int out_size) {
    const float* x1 = (const float*)d_in[0];
    const float* x2 = (const float*)d_in[1];
    const float* W1 = (const float*)d_in[2];
    const float* W2 = (const float*)d_in[3];
    const float* V  = (const float*)d_in[4];
    const float* b  = (const float*)d_in[5];
    float* out = (float*)d_out;

    prep_all<<<1280, 256>>>(x1, x2, W1, W2, V, b);

    cudaFuncSetAttribute(ntn_main,
                         cudaFuncAttributeMaxDynamicSharedMemorySize, SMEM_MAIN);
    dim3 grid(NN / 256, KK);
    ntn_main<<<grid, 256, SMEM_MAIN>>>(out);
}

// round 14
// speedup vs baseline: 1.1458x; 1.1458x over previous
#include <cuda_runtime.h>
#include <cuda_fp16.h>
#include <cstdint>

// NTN: out[n,k] = relu( cos(x1@W1[k], x2@W2[k]) + [x1,x2]@V[k] + b[k] )
// R14: R11 main kernel (validated). Three separate prep kernels (fusion
// regressed in R13); prep_p2 k-half split -> 256 blocks (2/SM) to hide LDS
// latency and fill all SMs.

#define NN 32768
#define DD 128
#define KK 32
#define EPSN 1e-8f

// ---------------- global scratch ----------------
__device__ uint4 gXfrag[2][2048][8][32];   // [mat][rowtile16][ds][lane] fp16 A-frags
__device__ uint4 gWh[32][2][2048];         // [k][chunk][granule] fp16 W
__device__ float gP2[(size_t)NN * KK];     // part2 + bias

// ---------------- helpers ----------------
static __device__ __forceinline__ uint32_t s2u(const void* p) {
    uint32_t a;
    asm("{ .reg .u64 t; cvta.to.shared.u64 t, %1; cvt.u32.u64 %0, t; }"
        : "=r"(a) : "l"(p));
    return a;
}
static __device__ __forceinline__ uint32_t packh2(float a, float b) {
    __half2 h = __floats2half2_rn(a, b);
    return *reinterpret_cast<uint32_t*>(&h);
}

#define LDSM4T(R, addr)                                                         \
    asm volatile("ldmatrix.sync.aligned.m8n8.x4.trans.shared.b16 {%0,%1,%2,%3},[%4];" \
                 : "=r"((R)[0]), "=r"((R)[1]), "=r"((R)[2]), "=r"((R)[3])       \
                 : "r"(addr))

#define HMMA(C, A, B0, B1)                                                      \
    asm volatile("mma.sync.aligned.m16n8k16.row.col.f32.f16.f16.f32 "           \
                 "{%0,%1,%2,%3},{%4,%5,%6,%7},{%8,%9},{%0,%1,%2,%3};"           \
                 : "+f"((C)[0]), "+f"((C)[1]), "+f"((C)[2]), "+f"((C)[3])       \
                 : "r"((A).x), "r"((A).y), "r"((A).z), "r"((A).w),              \
                   "r"(B0), "r"(B1))

static __device__ __forceinline__ void cp16(uint32_t dst, const void* src) {
    asm volatile("cp.async.cg.shared.global [%0], [%1], 16;"
                 :: "r"(dst), "l"(src) : "memory");
}
static __device__ __forceinline__ void cp_commit() {
    asm volatile("cp.async.commit_group;" ::: "memory");
}
template <int N>
static __device__ __forceinline__ void cp_wait() {
    asm volatile("cp.async.wait_group %0;" :: "n"(N) : "memory");
}

// ---------------- prep: X -> fp16 A-fragments ----------------
__global__ __launch_bounds__(256) void prep_x(const float* __restrict__ x1,
                                              const float* __restrict__ x2) {
    int wid  = (blockIdx.x * 256 + threadIdx.x) >> 5;   // 0..4095
    int lane = threadIdx.x & 31;
    int m  = wid >> 11;
    int rt = wid & 2047;
    const float* x = m ? x2 : x1;
    const float* p0 = x + (size_t)(rt * 16 + (lane >> 2)) * DD;
    const float* p1 = p0 + 8 * DD;
    const int c0 = (lane & 3) * 2;
    #pragma unroll
    for (int ds = 0; ds < 8; ds++) {
        int c = ds * 16 + c0;
        float2 v0 = *(const float2*)(p0 + c);
        float2 v1 = *(const float2*)(p1 + c);
        float2 v2 = *(const float2*)(p0 + c + 8);
        float2 v3 = *(const float2*)(p1 + c + 8);
        gXfrag[m][rt][ds][lane] = make_uint4(packh2(v0.x, v0.y), packh2(v1.x, v1.y),
                                             packh2(v2.x, v2.y), packh2(v3.x, v3.y));
    }
}

// ---------------- prep: W -> fp16 granules ----------------
// t bits: e8:0-2, d:3-9, mat:10, ch:11, k:12-16
__global__ __launch_bounds__(256) void prep_w(const float* __restrict__ W1,
                                              const float* __restrict__ W2) {
    int t   = blockIdx.x * 256 + threadIdx.x;   // 0..131071
    int e8  = t & 7;
    int d   = (t >> 3) & 127;
    int mat = (t >> 10) & 1;
    int ch  = (t >> 11) & 1;
    int k   = t >> 12;
    const float* w = (mat ? W2 : W1) + (size_t)k * DD * DD + (size_t)d * DD
                   + ch * 64 + e8 * 8;
    uint32_t hh[4];
    #pragma unroll
    for (int j = 0; j < 4; j++) hh[j] = packh2(w[2 * j], w[2 * j + 1]);
    gWh[k][ch][mat * 1024 + d * 8 + e8] = make_uint4(hh[0], hh[1], hh[2], hh[3]);
}

// ---------------- prep: part2 + bias (exact fp32), k-half split ----------------
// grid = 256 blocks: nblk = bid>>1 (0..127), kh = bid&1
__global__ __launch_bounds__(256) void prep_p2(const float* __restrict__ x1,
                                               const float* __restrict__ x2,
                                               const float* __restrict__ Vg,
                                               const float* __restrict__ bg) {
    __shared__ float Vs[16 * 256];
    __shared__ float bs[16];
    const int tid = threadIdx.x;
    const int kh  = blockIdx.x & 1;
    const int n   = (blockIdx.x >> 1) * 256 + tid;   // 0..32767
    const int kb  = kh * 16;
    for (int i = tid; i < 16 * 256; i += 256) Vs[i] = Vg[kb * 256 + i];
    if (tid < 16) bs[tid] = bg[kb + tid];
    __syncthreads();
    float acc[16];
    #pragma unroll
    for (int k = 0; k < 16; k++) acc[k] = bs[k];
    const float4* xa = (const float4*)(x1 + (size_t)n * DD);
    const float4* xb = (const float4*)(x2 + (size_t)n * DD);
    #pragma unroll 4
    for (int f = 0; f < 32; f++) {
        float4 xv = xa[f];
        #pragma unroll
        for (int k = 0; k < 16; k++) {
            float4 vv = *(const float4*)(&Vs[k * 256 + f * 4]);
            acc[k] = fmaf(xv.x, vv.x, fmaf(xv.y, vv.y,
                     fmaf(xv.z, vv.z, fmaf(xv.w, vv.w, acc[k]))));
        }
    }
    #pragma unroll 4
    for (int f = 0; f < 32; f++) {
        float4 xv = xb[f];
        #pragma unroll
        for (int k = 0; k < 16; k++) {
            float4 vv = *(const float4*)(&Vs[k * 256 + 128 + f * 4]);
            acc[k] = fmaf(xv.x, vv.x, fmaf(xv.y, vv.y,
                     fmaf(xv.z, vv.z, fmaf(xv.w, vv.w, acc[k]))));
        }
    }
    #pragma unroll
    for (int k = 0; k < 16; k++) gP2[(size_t)n * KK + kb + k] = acc[k];
}

// ---------------- main kernel (identical to R11) ----------------
#define WROWB 144                    // 128B data (64 fp16 cols) + 16B pad
#define WPL   (128 * WROWB)          // 18432 per mat tile
#define CHUNKB (2 * WPL)             // 36864 per chunk (2 mats)
#define OFF_STG (2 * CHUNKB)         // 73728 (both chunks resident)
#define SMEM_MAIN (OFF_STG + 8 * 4096)  // 106496

__global__ __launch_bounds__(256, 2)
void ntn_main(float* __restrict__ out) {
    extern __shared__ char smem[];
    const uint32_t sb = s2u(smem);
    const int tid  = threadIdx.x;
    const int lane = tid & 31;
    const int w    = tid >> 5;     // warp 0..7: rows 32*w .. +31 (of 256)
    const int k     = blockIdx.y;
    const int rbase = blockIdx.x * 256;
    const int rtb   = blockIdx.x * 16 + w * 2;

    // ---- cp.async BOTH chunks upfront (disjoint buffers) ----
    #pragma unroll
    for (int ch = 0; ch < 2; ch++) {
        #pragma unroll
        for (int i = 0; i < 8; i++) {
            int idx = tid + 256 * i;            // 0..2047
            int mp  = idx >> 10;
            int d   = (idx >> 3) & 127;
            int e8  = idx & 7;
            cp16(sb + ch * CHUNKB + mp * WPL + d * WROWB + e8 * 16,
                 &gWh[k][ch][idx]);
        }
        cp_commit();
    }

    const int arow  = (lane & 7) + ((lane >> 3) & 1) * 8;
    const int half8 = lane >> 4;
    const uint32_t boff = (uint32_t)(arow * WROWB + half8 * 16);
    char* stg = smem + OFF_STG + w * 4096 + lane * 8;

    // ---- A register double-buffer: prefetch step (g=0, ds=0) ----
    uint4 a[2][2];
    a[0][0] = gXfrag[0][rtb][0][lane];
    a[0][1] = gXfrag[0][rtb + 1][0][lane];

    float dv[4]  = {0.f, 0.f, 0.f, 0.f};
    float n1v[4] = {0.f, 0.f, 0.f, 0.f};
    float n2v[4] = {0.f, 0.f, 0.f, 0.f};

    cp_wait<1>();
    __syncthreads();

    #pragma unroll 1
    for (int c = 0; c < 2; c++) {
        if (c == 1) { cp_wait<0>(); __syncthreads(); }
        const uint32_t cbuf = sb + c * CHUNKB;

        #pragma unroll 1
        for (int g = 0; g < 2; g++) {
            float cc[2][8][4];
            #pragma unroll
            for (int mt = 0; mt < 2; mt++)
                #pragma unroll
                for (int nt = 0; nt < 8; nt++)
                    #pragma unroll
                    for (int q = 0; q < 4; q++) cc[mt][nt][q] = 0.f;

            #pragma unroll
            for (int ds = 0; ds < 8; ds++) {
                const int cur = ds & 1, nxt = cur ^ 1;
                const int gn = (ds < 7) ? g : (g ^ 1);
                const int dn = (ds < 7) ? (ds + 1) : 0;
                a[nxt][0] = gXfrag[gn][rtb][dn][lane];
                a[nxt][1] = gXfrag[gn][rtb + 1][dn][lane];

                uint32_t bb[4][4];
                const uint32_t tb = cbuf + g * WPL + (uint32_t)(ds * 16 * WROWB) + boff;
                LDSM4T(bb[0], tb);
                LDSM4T(bb[1], tb + 32);
                LDSM4T(bb[2], tb + 64);
                LDSM4T(bb[3], tb + 96);

                #pragma unroll
                for (int cb = 0; cb < 4; cb++) {
                    HMMA(cc[0][cb * 2],     a[cur][0], bb[cb][0], bb[cb][1]);
                    HMMA(cc[1][cb * 2],     a[cur][1], bb[cb][0], bb[cb][1]);
                    HMMA(cc[0][cb * 2 + 1], a[cur][0], bb[cb][2], bb[cb][3]);
                    HMMA(cc[1][cb * 2 + 1], a[cur][1], bb[cb][2], bb[cb][3]);
                }
            }

            if (g == 0) {
                #pragma unroll
                for (int mt = 0; mt < 2; mt++)
                    #pragma unroll
                    for (int nt = 0; nt < 8; nt++) {
                        uint2 pv;
                        pv.x = packh2(cc[mt][nt][0], cc[mt][nt][1]);
                        pv.y = packh2(cc[mt][nt][2], cc[mt][nt][3]);
                        *(uint2*)(stg + (mt * 8 + nt) * 256) = pv;
                    }
            } else {
                #pragma unroll
                for (int mt = 0; mt < 2; mt++)
                    #pragma unroll
                    for (int nt = 0; nt < 8; nt++) {
                        uint2 pv = *(const uint2*)(stg + (mt * 8 + nt) * 256);
                        float2 f0 = __half22float2(*reinterpret_cast<__half2*>(&pv.x));
                        float2 f1 = __half22float2(*reinterpret_cast<__half2*>(&pv.y));
                        const int s0 = mt * 2;
                        float b0 = cc[mt][nt][0], b1 = cc[mt][nt][1];
                        float b2 = cc[mt][nt][2], b3 = cc[mt][nt][3];
                        dv[s0]      = fmaf(f0.x, b0, fmaf(f0.y, b1, dv[s0]));
                        n1v[s0]     = fmaf(f0.x, f0.x, fmaf(f0.y, f0.y, n1v[s0]));
                        n2v[s0]     = fmaf(b0, b0, fmaf(b1, b1, n2v[s0]));
                        dv[s0 + 1]  = fmaf(f1.x, b2, fmaf(f1.y, b3, dv[s0 + 1]));
                        n1v[s0 + 1] = fmaf(f1.x, f1.x, fmaf(f1.y, f1.y, n1v[s0 + 1]));
                        n2v[s0 + 1] = fmaf(b2, b2, fmaf(b3, b3, n2v[s0 + 1]));
                    }
            }
        }
    }

    // ---- lane reduce (4 lanes share a row); rows are warp-exclusive ----
    #pragma unroll
    for (int s = 0; s < 4; s++) {
        #pragma unroll
        for (int off = 1; off <= 2; off <<= 1) {
            dv[s]  += __shfl_xor_sync(0xffffffffu, dv[s],  off);
            n1v[s] += __shfl_xor_sync(0xffffffffu, n1v[s], off);
            n2v[s] += __shfl_xor_sync(0xffffffffu, n2v[s], off);
        }
    }
    if ((lane & 3) == 0) {
        #pragma unroll
        for (int s = 0; s < 4; s++) {
            const int row = w * 32 + (s >> 1) * 16 + (s & 1) * 8 + (lane >> 2);
            float s1 = fmaxf(sqrtf(n1v[s]), EPSN);
            float s2 = fmaxf(sqrtf(n2v[s]), EPSN);
            float v  = dv[s] / (s1 * s2) + gP2[(size_t)(rbase + row) * KK + k];
            out[(size_t)(rbase + row) * KK + k] = fmaxf(v, 0.f);
        }
    }
}

extern "C" void kernel_launch(void* const* d_in, const int* in_sizes, int n_in,
                              void* d_out, int out_size) {
    const float* x1 = (const float*)d_in[0];
    const float* x2 = (const float*)d_in[1];
    const float* W1 = (const float*)d_in[2];
    const float* W2 = (const float*)d_in[3];
    const float* V  = (const float*)d_in[4];
    const float* b  = (const float*)d_in[5];
    float* out = (float*)d_out;

    prep_x<<<512, 256>>>(x1, x2);
    prep_w<<<512, 256>>>(W1, W2);
    prep_p2<<<256, 256>>>(x1, x2, V, b);

    cudaFuncSetAttribute(ntn_main,
                         cudaFuncAttributeMaxDynamicSharedMemorySize, SMEM_MAIN);
    dim3 grid(NN / 256, KK);
    ntn_main<<<grid, 256, SMEM_MAIN>>>(out);
}

// round 15
// speedup vs baseline: 1.3537x; 1.1815x over previous
#include <cuda_runtime.h>
#include <cuda_fp16.h>
#include <cstdint>

// NTN: out[n,k] = relu( cos(x1@W1[k], x2@W2[k]) + [x1,x2]@V[k] + b[k] )
// R15: R11 main kernel (validated). part2 moved to tensor cores (prep_p2h):
// GEMM [N x 2D]·[2D x K] in fp16 HMMA reusing gXfrag A-fragments, V in a
// [256 d][32 k] fp16 smem tile (80B pitch), bias fused. Replaces the 31us
// FMA-bound fp32 prep_p2.

#define NN 32768
#define DD 128
#define KK 32
#define EPSN 1e-8f

// ---------------- global scratch ----------------
__device__ uint4 gXfrag[2][2048][8][32];   // [mat][rowtile16][ds][lane] fp16 A-frags
__device__ uint4 gWh[32][2][2048];         // [k][chunk][granule] fp16 W
__device__ float gP2[(size_t)NN * KK];     // part2 + bias

// ---------------- helpers ----------------
static __device__ __forceinline__ uint32_t s2u(const void* p) {
    uint32_t a;
    asm("{ .reg .u64 t; cvta.to.shared.u64 t, %1; cvt.u32.u64 %0, t; }"
        : "=r"(a) : "l"(p));
    return a;
}
static __device__ __forceinline__ uint32_t packh2(float a, float b) {
    __half2 h = __floats2half2_rn(a, b);
    return *reinterpret_cast<uint32_t*>(&h);
}

#define LDSM4T(R, addr)                                                         \
    asm volatile("ldmatrix.sync.aligned.m8n8.x4.trans.shared.b16 {%0,%1,%2,%3},[%4];" \
                 : "=r"((R)[0]), "=r"((R)[1]), "=r"((R)[2]), "=r"((R)[3])       \
                 : "r"(addr))

#define HMMA(C, A, B0, B1)                                                      \
    asm volatile("mma.sync.aligned.m16n8k16.row.col.f32.f16.f16.f32 "           \
                 "{%0,%1,%2,%3},{%4,%5,%6,%7},{%8,%9},{%0,%1,%2,%3};"           \
                 : "+f"((C)[0]), "+f"((C)[1]), "+f"((C)[2]), "+f"((C)[3])       \
                 : "r"((A).x), "r"((A).y), "r"((A).z), "r"((A).w),              \
                   "r"(B0), "r"(B1))

static __device__ __forceinline__ void cp16(uint32_t dst, const void* src) {
    asm volatile("cp.async.cg.shared.global [%0], [%1], 16;"
                 :: "r"(dst), "l"(src) : "memory");
}
static __device__ __forceinline__ void cp_commit() {
    asm volatile("cp.async.commit_group;" ::: "memory");
}
template <int N>
static __device__ __forceinline__ void cp_wait() {
    asm volatile("cp.async.wait_group %0;" :: "n"(N) : "memory");
}

// ---------------- prep: X -> fp16 A-fragments ----------------
__global__ __launch_bounds__(256) void prep_x(const float* __restrict__ x1,
                                              const float* __restrict__ x2) {
    int wid  = (blockIdx.x * 256 + threadIdx.x) >> 5;   // 0..4095
    int lane = threadIdx.x & 31;
    int m  = wid >> 11;
    int rt = wid & 2047;
    const float* x = m ? x2 : x1;
    const float* p0 = x + (size_t)(rt * 16 + (lane >> 2)) * DD;
    const float* p1 = p0 + 8 * DD;
    const int c0 = (lane & 3) * 2;
    #pragma unroll
    for (int ds = 0; ds < 8; ds++) {
        int c = ds * 16 + c0;
        float2 v0 = *(const float2*)(p0 + c);
        float2 v1 = *(const float2*)(p1 + c);
        float2 v2 = *(const float2*)(p0 + c + 8);
        float2 v3 = *(const float2*)(p1 + c + 8);
        gXfrag[m][rt][ds][lane] = make_uint4(packh2(v0.x, v0.y), packh2(v1.x, v1.y),
                                             packh2(v2.x, v2.y), packh2(v3.x, v3.y));
    }
}

// ---------------- prep: W -> fp16 granules ----------------
// t bits: e8:0-2, d:3-9, mat:10, ch:11, k:12-16
__global__ __launch_bounds__(256) void prep_w(const float* __restrict__ W1,
                                              const float* __restrict__ W2) {
    int t   = blockIdx.x * 256 + threadIdx.x;   // 0..131071
    int e8  = t & 7;
    int d   = (t >> 3) & 127;
    int mat = (t >> 10) & 1;
    int ch  = (t >> 11) & 1;
    int k   = t >> 12;
    const float* w = (mat ? W2 : W1) + (size_t)k * DD * DD + (size_t)d * DD
                   + ch * 64 + e8 * 8;
    uint32_t hh[4];
    #pragma unroll
    for (int j = 0; j < 4; j++) hh[j] = packh2(w[2 * j], w[2 * j + 1]);
    gWh[k][ch][mat * 1024 + d * 8 + e8] = make_uint4(hh[0], hh[1], hh[2], hh[3]);
}

// ---------------- prep: part2 + bias via tensor cores ----------------
// GEMM [NN x 256]·[256 x 32] with A from gXfrag (must run after prep_x).
// V smem tile: [256 d][32 k] fp16, pitch 80B (64B data + 16B pad).
#define VROWB 80
__global__ __launch_bounds__(256) void prep_p2h(const float* __restrict__ Vg,
                                                const float* __restrict__ bg) {
    __shared__ __align__(16) char vsm[256 * VROWB];   // 20480 B
    __shared__ float bs[KK];
    const int tid  = threadIdx.x;
    const int lane = tid & 31;
    const int w    = tid >> 5;

    // fill V smem transposed: row d holds V[k][d] for k=0..31 (coalesced in d)
    {
        const int d = tid;                     // 0..255
        __half* row = (__half*)(vsm + d * VROWB);
        #pragma unroll 8
        for (int kc = 0; kc < KK; kc++)
            row[kc] = __float2half_rn(Vg[kc * 256 + d]);
    }
    if (tid < KK) bs[tid] = bg[tid];
    __syncthreads();

    const uint32_t sbv = s2u(vsm);
    const int arow  = (lane & 7) + ((lane >> 3) & 1) * 8;
    const int half8 = lane >> 4;
    const uint32_t boff = (uint32_t)(arow * VROWB + half8 * 16);
    const int rtb = blockIdx.x * 16 + w * 2;   // two rowtiles per warp

    float cc[2][4][4];
    #pragma unroll
    for (int mt = 0; mt < 2; mt++)
        #pragma unroll
        for (int nt = 0; nt < 4; nt++)
            #pragma unroll
            for (int q = 0; q < 4; q++) cc[mt][nt][q] = 0.f;

    #pragma unroll
    for (int ds = 0; ds < 16; ds++) {
        const int m  = ds >> 3;
        const int dl = ds & 7;
        uint4 a0 = gXfrag[m][rtb][dl][lane];
        uint4 a1 = gXfrag[m][rtb + 1][dl][lane];
        uint32_t bb[2][4];
        const uint32_t tb = sbv + (uint32_t)(ds * 16 * VROWB) + boff;
        LDSM4T(bb[0], tb);
        LDSM4T(bb[1], tb + 32);
        #pragma unroll
        for (int cb = 0; cb < 2; cb++) {
            HMMA(cc[0][cb * 2],     a0, bb[cb][0], bb[cb][1]);
            HMMA(cc[1][cb * 2],     a1, bb[cb][0], bb[cb][1]);
            HMMA(cc[0][cb * 2 + 1], a0, bb[cb][2], bb[cb][3]);
            HMMA(cc[1][cb * 2 + 1], a1, bb[cb][2], bb[cb][3]);
        }
    }

    // epilogue: add bias, store float2 pairs
    const int rb = blockIdx.x * 256 + w * 32;
    #pragma unroll
    for (int mt = 0; mt < 2; mt++)
        #pragma unroll
        for (int nt = 0; nt < 4; nt++) {
            const int col  = nt * 8 + 2 * (lane & 3);
            const int row0 = rb + mt * 16 + (lane >> 2);
            float2 v0 = make_float2(cc[mt][nt][0] + bs[col], cc[mt][nt][1] + bs[col + 1]);
            float2 v1 = make_float2(cc[mt][nt][2] + bs[col], cc[mt][nt][3] + bs[col + 1]);
            *(float2*)&gP2[(size_t)row0 * KK + col]       = v0;
            *(float2*)&gP2[(size_t)(row0 + 8) * KK + col] = v1;
        }
}

// ---------------- main kernel (identical to R11) ----------------
#define WROWB 144                    // 128B data (64 fp16 cols) + 16B pad
#define WPL   (128 * WROWB)          // 18432 per mat tile
#define CHUNKB (2 * WPL)             // 36864 per chunk (2 mats)
#define OFF_STG (2 * CHUNKB)         // 73728 (both chunks resident)
#define SMEM_MAIN (OFF_STG + 8 * 4096)  // 106496

__global__ __launch_bounds__(256, 2)
void ntn_main(float* __restrict__ out) {
    extern __shared__ char smem[];
    const uint32_t sb = s2u(smem);
    const int tid  = threadIdx.x;
    const int lane = tid & 31;
    const int w    = tid >> 5;     // warp 0..7: rows 32*w .. +31 (of 256)
    const int k     = blockIdx.y;
    const int rbase = blockIdx.x * 256;
    const int rtb   = blockIdx.x * 16 + w * 2;

    // ---- cp.async BOTH chunks upfront (disjoint buffers) ----
    #pragma unroll
    for (int ch = 0; ch < 2; ch++) {
        #pragma unroll
        for (int i = 0; i < 8; i++) {
            int idx = tid + 256 * i;            // 0..2047
            int mp  = idx >> 10;
            int d   = (idx >> 3) & 127;
            int e8  = idx & 7;
            cp16(sb + ch * CHUNKB + mp * WPL + d * WROWB + e8 * 16,
                 &gWh[k][ch][idx]);
        }
        cp_commit();
    }

    const int arow  = (lane & 7) + ((lane >> 3) & 1) * 8;
    const int half8 = lane >> 4;
    const uint32_t boff = (uint32_t)(arow * WROWB + half8 * 16);
    char* stg = smem + OFF_STG + w * 4096 + lane * 8;

    // ---- A register double-buffer: prefetch step (g=0, ds=0) ----
    uint4 a[2][2];
    a[0][0] = gXfrag[0][rtb][0][lane];
    a[0][1] = gXfrag[0][rtb + 1][0][lane];

    float dv[4]  = {0.f, 0.f, 0.f, 0.f};
    float n1v[4] = {0.f, 0.f, 0.f, 0.f};
    float n2v[4] = {0.f, 0.f, 0.f, 0.f};

    cp_wait<1>();
    __syncthreads();

    #pragma unroll 1
    for (int c = 0; c < 2; c++) {
        if (c == 1) { cp_wait<0>(); __syncthreads(); }
        const uint32_t cbuf = sb + c * CHUNKB;

        #pragma unroll 1
        for (int g = 0; g < 2; g++) {
            float cc[2][8][4];
            #pragma unroll
            for (int mt = 0; mt < 2; mt++)
                #pragma unroll
                for (int nt = 0; nt < 8; nt++)
                    #pragma unroll
                    for (int q = 0; q < 4; q++) cc[mt][nt][q] = 0.f;

            #pragma unroll
            for (int ds = 0; ds < 8; ds++) {
                const int cur = ds & 1, nxt = cur ^ 1;
                const int gn = (ds < 7) ? g : (g ^ 1);
                const int dn = (ds < 7) ? (ds + 1) : 0;
                a[nxt][0] = gXfrag[gn][rtb][dn][lane];
                a[nxt][1] = gXfrag[gn][rtb + 1][dn][lane];

                uint32_t bb[4][4];
                const uint32_t tb = cbuf + g * WPL + (uint32_t)(ds * 16 * WROWB) + boff;
                LDSM4T(bb[0], tb);
                LDSM4T(bb[1], tb + 32);
                LDSM4T(bb[2], tb + 64);
                LDSM4T(bb[3], tb + 96);

                #pragma unroll
                for (int cb = 0; cb < 4; cb++) {
                    HMMA(cc[0][cb * 2],     a[cur][0], bb[cb][0], bb[cb][1]);
                    HMMA(cc[1][cb * 2],     a[cur][1], bb[cb][0], bb[cb][1]);
                    HMMA(cc[0][cb * 2 + 1], a[cur][0], bb[cb][2], bb[cb][3]);
                    HMMA(cc[1][cb * 2 + 1], a[cur][1], bb[cb][2], bb[cb][3]);
                }
            }

            if (g == 0) {
                #pragma unroll
                for (int mt = 0; mt < 2; mt++)
                    #pragma unroll
                    for (int nt = 0; nt < 8; nt++) {
                        uint2 pv;
                        pv.x = packh2(cc[mt][nt][0], cc[mt][nt][1]);
                        pv.y = packh2(cc[mt][nt][2], cc[mt][nt][3]);
                        *(uint2*)(stg + (mt * 8 + nt) * 256) = pv;
                    }
            } else {
                #pragma unroll
                for (int mt = 0; mt < 2; mt++)
                    #pragma unroll
                    for (int nt = 0; nt < 8; nt++) {
                        uint2 pv = *(const uint2*)(stg + (mt * 8 + nt) * 256);
                        float2 f0 = __half22float2(*reinterpret_cast<__half2*>(&pv.x));
                        float2 f1 = __half22float2(*reinterpret_cast<__half2*>(&pv.y));
                        const int s0 = mt * 2;
                        float b0 = cc[mt][nt][0], b1 = cc[mt][nt][1];
                        float b2 = cc[mt][nt][2], b3 = cc[mt][nt][3];
                        dv[s0]      = fmaf(f0.x, b0, fmaf(f0.y, b1, dv[s0]));
                        n1v[s0]     = fmaf(f0.x, f0.x, fmaf(f0.y, f0.y, n1v[s0]));
                        n2v[s0]     = fmaf(b0, b0, fmaf(b1, b1, n2v[s0]));
                        dv[s0 + 1]  = fmaf(f1.x, b2, fmaf(f1.y, b3, dv[s0 + 1]));
                        n1v[s0 + 1] = fmaf(f1.x, f1.x, fmaf(f1.y, f1.y, n1v[s0 + 1]));
                        n2v[s0 + 1] = fmaf(b2, b2, fmaf(b3, b3, n2v[s0 + 1]));
                    }
            }
        }
    }

    // ---- lane reduce (4 lanes share a row); rows are warp-exclusive ----
    #pragma unroll
    for (int s = 0; s < 4; s++) {
        #pragma unroll
        for (int off = 1; off <= 2; off <<= 1) {
            dv[s]  += __shfl_xor_sync(0xffffffffu, dv[s],  off);
            n1v[s] += __shfl_xor_sync(0xffffffffu, n1v[s], off);
            n2v[s] += __shfl_xor_sync(0xffffffffu, n2v[s], off);
        }
    }
    if ((lane & 3) == 0) {
        #pragma unroll
        for (int s = 0; s < 4; s++) {
            const int row = w * 32 + (s >> 1) * 16 + (s & 1) * 8 + (lane >> 2);
            float s1 = fmaxf(sqrtf(n1v[s]), EPSN);
            float s2 = fmaxf(sqrtf(n2v[s]), EPSN);
            float v  = dv[s] / (s1 * s2) + gP2[(size_t)(rbase + row) * KK + k];
            out[(size_t)(rbase + row) * KK + k] = fmaxf(v, 0.f);
        }
    }
}

extern "C" void kernel_launch(void* const* d_in, const int* in_sizes, int n_in,
                              void* d_out, int out_size) {
    const float* x1 = (const float*)d_in[0];
    const float* x2 = (const float*)d_in[1];
    const float* W1 = (const float*)d_in[2];
    const float* W2 = (const float*)d_in[3];
    const float* V  = (const float*)d_in[4];
    const float* b  = (const float*)d_in[5];
    float* out = (float*)d_out;

    prep_x<<<512, 256>>>(x1, x2);
    prep_w<<<512, 256>>>(W1, W2);
    prep_p2h<<<NN / 256, 256>>>(V, b);   // reads gXfrag: must follow prep_x

    cudaFuncSetAttribute(ntn_main,
                         cudaFuncAttributeMaxDynamicSharedMemorySize, SMEM_MAIN);
    dim3 grid(NN / 256, KK);
    ntn_main<<<grid, 256, SMEM_MAIN>>>(out);
}

// round 16
// speedup vs baseline: 1.3553x; 1.0012x over previous
#include <cuda_runtime.h>
#include <cuda_fp16.h>
#include <cstdint>

// NTN: out[n,k] = relu( cos(x1@W1[k], x2@W2[k]) + [x1,x2]@V[k] + b[k] )
// R16: fp16 HMMA with BOTH operands as precomputed mma fragments in global.
// No smem W, no cp.async, no __syncthreads in main (warp-private staging
// only). B fragments are identical across warps -> L1 broadcast.

#define NN 32768
#define DD 128
#define KK 32
#define EPSN 1e-8f

// ---------------- global scratch ----------------
__device__ uint4 gXfrag[2][2048][8][32];       // [mat][rowtile16][ds][lane] A-frags
__device__ uint4 gWfrag[32][2][2][8][4][32];   // [k][g][eh][ds][cb][lane] B-frags (4MB)
__device__ float gP2[(size_t)NN * KK];         // part2 + bias

// ---------------- helpers ----------------
static __device__ __forceinline__ uint32_t s2u(const void* p) {
    uint32_t a;
    asm("{ .reg .u64 t; cvta.to.shared.u64 t, %1; cvt.u32.u64 %0, t; }"
        : "=r"(a) : "l"(p));
    return a;
}
static __device__ __forceinline__ uint32_t packh2(float a, float b) {
    __half2 h = __floats2half2_rn(a, b);
    return *reinterpret_cast<uint32_t*>(&h);
}

#define LDSM4T(R, addr)                                                         \
    asm volatile("ldmatrix.sync.aligned.m8n8.x4.trans.shared.b16 {%0,%1,%2,%3},[%4];" \
                 : "=r"((R)[0]), "=r"((R)[1]), "=r"((R)[2]), "=r"((R)[3])       \
                 : "r"(addr))

#define HMMA(C, A, B0, B1)                                                      \
    asm volatile("mma.sync.aligned.m16n8k16.row.col.f32.f16.f16.f32 "           \
                 "{%0,%1,%2,%3},{%4,%5,%6,%7},{%8,%9},{%0,%1,%2,%3};"           \
                 : "+f"((C)[0]), "+f"((C)[1]), "+f"((C)[2]), "+f"((C)[3])       \
                 : "r"((A).x), "r"((A).y), "r"((A).z), "r"((A).w),              \
                   "r"(B0), "r"(B1))

// ---------------- prep: X -> fp16 A-fragments ----------------
__global__ __launch_bounds__(256) void prep_x(const float* __restrict__ x1,
                                              const float* __restrict__ x2) {
    int wid  = (blockIdx.x * 256 + threadIdx.x) >> 5;   // 0..4095
    int lane = threadIdx.x & 31;
    int m  = wid >> 11;
    int rt = wid & 2047;
    const float* x = m ? x2 : x1;
    const float* p0 = x + (size_t)(rt * 16 + (lane >> 2)) * DD;
    const float* p1 = p0 + 8 * DD;
    const int c0 = (lane & 3) * 2;
    #pragma unroll
    for (int ds = 0; ds < 8; ds++) {
        int c = ds * 16 + c0;
        float2 v0 = *(const float2*)(p0 + c);
        float2 v1 = *(const float2*)(p1 + c);
        float2 v2 = *(const float2*)(p0 + c + 8);
        float2 v3 = *(const float2*)(p1 + c + 8);
        gXfrag[m][rt][ds][lane] = make_uint4(packh2(v0.x, v0.y), packh2(v1.x, v1.y),
                                             packh2(v2.x, v2.y), packh2(v3.x, v3.y));
    }
}

// ---------------- prep: W -> fp16 B-fragments (m16n8k16 spec layout) ----------
// warp-task wt: cb:0-1, ds:2-4, eh:5, g:6, k:7-11
__global__ __launch_bounds__(256) void prep_w(const float* __restrict__ W1,
                                              const float* __restrict__ W2) {
    int t    = blockIdx.x * 256 + threadIdx.x;   // 0..131071
    int lane = t & 31;
    int wt   = t >> 5;                           // 0..4095
    int cb = wt & 3;
    int ds = (wt >> 2) & 7;
    int eh = (wt >> 5) & 1;
    int g  = (wt >> 6) & 1;
    int k  = wt >> 7;
    const float* w = (g ? W2 : W1) + (size_t)k * DD * DD;
    const int tg = lane & 3, gg = lane >> 2;
    const int d0 = ds * 16 + tg * 2;
    const int e0 = eh * 64 + cb * 16 + gg;
    uint4 f;
    f.x = packh2(w[(size_t)d0 * DD + e0],       w[(size_t)(d0 + 1) * DD + e0]);
    f.y = packh2(w[(size_t)(d0 + 8) * DD + e0], w[(size_t)(d0 + 9) * DD + e0]);
    f.z = packh2(w[(size_t)d0 * DD + e0 + 8],       w[(size_t)(d0 + 1) * DD + e0 + 8]);
    f.w = packh2(w[(size_t)(d0 + 8) * DD + e0 + 8], w[(size_t)(d0 + 9) * DD + e0 + 8]);
    gWfrag[k][g][eh][ds][cb][lane] = f;
}

// ---------------- prep: part2 + bias via tensor cores (unchanged R15) -------
#define VROWB 80
__global__ __launch_bounds__(256) void prep_p2h(const float* __restrict__ Vg,
                                                const float* __restrict__ bg) {
    __shared__ __align__(16) char vsm[256 * VROWB];
    __shared__ float bs[KK];
    const int tid  = threadIdx.x;
    const int lane = tid & 31;
    const int w    = tid >> 5;
    {
        const int d = tid;
        __half* row = (__half*)(vsm + d * VROWB);
        #pragma unroll 8
        for (int kc = 0; kc < KK; kc++)
            row[kc] = __float2half_rn(Vg[kc * 256 + d]);
    }
    if (tid < KK) bs[tid] = bg[tid];
    __syncthreads();

    const uint32_t sbv = s2u(vsm);
    const int arow  = (lane & 7) + ((lane >> 3) & 1) * 8;
    const int half8 = lane >> 4;
    const uint32_t boff = (uint32_t)(arow * VROWB + half8 * 16);
    const int rtb = blockIdx.x * 16 + w * 2;

    float cc[2][4][4];
    #pragma unroll
    for (int mt = 0; mt < 2; mt++)
        #pragma unroll
        for (int nt = 0; nt < 4; nt++)
            #pragma unroll
            for (int q = 0; q < 4; q++) cc[mt][nt][q] = 0.f;

    #pragma unroll
    for (int ds = 0; ds < 16; ds++) {
        const int m  = ds >> 3;
        const int dl = ds & 7;
        uint4 a0 = gXfrag[m][rtb][dl][lane];
        uint4 a1 = gXfrag[m][rtb + 1][dl][lane];
        uint32_t bb[2][4];
        const uint32_t tb = sbv + (uint32_t)(ds * 16 * VROWB) + boff;
        LDSM4T(bb[0], tb);
        LDSM4T(bb[1], tb + 32);
        #pragma unroll
        for (int cb = 0; cb < 2; cb++) {
            HMMA(cc[0][cb * 2],     a0, bb[cb][0], bb[cb][1]);
            HMMA(cc[1][cb * 2],     a1, bb[cb][0], bb[cb][1]);
            HMMA(cc[0][cb * 2 + 1], a0, bb[cb][2], bb[cb][3]);
            HMMA(cc[1][cb * 2 + 1], a1, bb[cb][2], bb[cb][3]);
        }
    }

    const int rb = blockIdx.x * 256 + w * 32;
    #pragma unroll
    for (int mt = 0; mt < 2; mt++)
        #pragma unroll
        for (int nt = 0; nt < 4; nt++) {
            const int col  = nt * 8 + 2 * (lane & 3);
            const int row0 = rb + mt * 16 + (lane >> 2);
            float2 v0 = make_float2(cc[mt][nt][0] + bs[col], cc[mt][nt][1] + bs[col + 1]);
            float2 v1 = make_float2(cc[mt][nt][2] + bs[col], cc[mt][nt][3] + bs[col + 1]);
            *(float2*)&gP2[(size_t)row0 * KK + col]       = v0;
            *(float2*)&gP2[(size_t)(row0 + 8) * KK + col] = v1;
        }
}

// ---------------- main kernel: fragment-direct, barrier-free ----------------
#define SMEM_MAIN 32768   // 8 warps x 4KB warp-private staging

__global__ __launch_bounds__(256, 2)
void ntn_main(float* __restrict__ out) {
    extern __shared__ char smem[];
    const int tid  = threadIdx.x;
    const int lane = tid & 31;
    const int w    = tid >> 5;     // warp 0..7: rows 32*w .. +31 (of 256)
    const int k     = blockIdx.y;
    const int rbase = blockIdx.x * 256;
    const int rtb   = blockIdx.x * 16 + w * 2;
    char* stg = smem + w * 4096 + lane * 8;

    // ---- A register double-buffer: prefetch (g=0, ds=0) ----
    uint4 a[2][2];
    a[0][0] = gXfrag[0][rtb][0][lane];
    a[0][1] = gXfrag[0][rtb + 1][0][lane];

    float dv[4]  = {0.f, 0.f, 0.f, 0.f};
    float n1v[4] = {0.f, 0.f, 0.f, 0.f};
    float n2v[4] = {0.f, 0.f, 0.f, 0.f};

    #pragma unroll 1
    for (int c = 0; c < 2; c++) {
        #pragma unroll 1
        for (int g = 0; g < 2; g++) {
            float cc[2][8][4];
            #pragma unroll
            for (int mt = 0; mt < 2; mt++)
                #pragma unroll
                for (int nt = 0; nt < 8; nt++)
                    #pragma unroll
                    for (int q = 0; q < 4; q++) cc[mt][nt][q] = 0.f;

            const uint4* bbase = &gWfrag[k][g][c][0][0][lane];

            #pragma unroll
            for (int ds = 0; ds < 8; ds++) {
                const int cur = ds & 1, nxt = cur ^ 1;
                // prefetch next step's A (A independent of c; wraps across passes)
                const int gn = (ds < 7) ? g : (g ^ 1);
                const int dn = (ds < 7) ? (ds + 1) : 0;
                a[nxt][0] = gXfrag[gn][rtb][dn][lane];
                a[nxt][1] = gXfrag[gn][rtb + 1][dn][lane];

                // B fragments: same address across all warps -> L1 broadcast
                uint4 bb[4];
                #pragma unroll
                for (int cb = 0; cb < 4; cb++) bb[cb] = bbase[(ds * 4 + cb) * 32];

                #pragma unroll
                for (int cb = 0; cb < 4; cb++) {
                    HMMA(cc[0][cb * 2],     a[cur][0], bb[cb].x, bb[cb].y);
                    HMMA(cc[1][cb * 2],     a[cur][1], bb[cb].x, bb[cb].y);
                    HMMA(cc[0][cb * 2 + 1], a[cur][0], bb[cb].z, bb[cb].w);
                    HMMA(cc[1][cb * 2 + 1], a[cur][1], bb[cb].z, bb[cb].w);
                }
            }

            if (g == 0) {
                // stage x1t tile as fp16 pairs (warp-private; no sync needed)
                #pragma unroll
                for (int mt = 0; mt < 2; mt++)
                    #pragma unroll
                    for (int nt = 0; nt < 8; nt++) {
                        uint2 pv;
                        pv.x = packh2(cc[mt][nt][0], cc[mt][nt][1]);
                        pv.y = packh2(cc[mt][nt][2], cc[mt][nt][3]);
                        *(uint2*)(stg + (mt * 8 + nt) * 256) = pv;
                    }
            } else {
                // fold: x1t (staged fp16) against x2t (cc)
                #pragma unroll
                for (int mt = 0; mt < 2; mt++)
                    #pragma unroll
                    for (int nt = 0; nt < 8; nt++) {
                        uint2 pv = *(const uint2*)(stg + (mt * 8 + nt) * 256);
                        float2 f0 = __half22float2(*reinterpret_cast<__half2*>(&pv.x));
                        float2 f1 = __half22float2(*reinterpret_cast<__half2*>(&pv.y));
                        const int s0 = mt * 2;
                        float b0 = cc[mt][nt][0], b1 = cc[mt][nt][1];
                        float b2 = cc[mt][nt][2], b3 = cc[mt][nt][3];
                        dv[s0]      = fmaf(f0.x, b0, fmaf(f0.y, b1, dv[s0]));
                        n1v[s0]     = fmaf(f0.x, f0.x, fmaf(f0.y, f0.y, n1v[s0]));
                        n2v[s0]     = fmaf(b0, b0, fmaf(b1, b1, n2v[s0]));
                        dv[s0 + 1]  = fmaf(f1.x, b2, fmaf(f1.y, b3, dv[s0 + 1]));
                        n1v[s0 + 1] = fmaf(f1.x, f1.x, fmaf(f1.y, f1.y, n1v[s0 + 1]));
                        n2v[s0 + 1] = fmaf(b2, b2, fmaf(b3, b3, n2v[s0 + 1]));
                    }
            }
        }
    }

    // ---- lane reduce (4 lanes share a row); rows are warp-exclusive ----
    #pragma unroll
    for (int s = 0; s < 4; s++) {
        #pragma unroll
        for (int off = 1; off <= 2; off <<= 1) {
            dv[s]  += __shfl_xor_sync(0xffffffffu, dv[s],  off);
            n1v[s] += __shfl_xor_sync(0xffffffffu, n1v[s], off);
            n2v[s] += __shfl_xor_sync(0xffffffffu, n2v[s], off);
        }
    }
    if ((lane & 3) == 0) {
        #pragma unroll
        for (int s = 0; s < 4; s++) {
            const int row = w * 32 + (s >> 1) * 16 + (s & 1) * 8 + (lane >> 2);
            float s1 = fmaxf(sqrtf(n1v[s]), EPSN);
            float s2 = fmaxf(sqrtf(n2v[s]), EPSN);
            float v  = dv[s] / (s1 * s2) + gP2[(size_t)(rbase + row) * KK + k];
            out[(size_t)(rbase + row) * KK + k] = fmaxf(v, 0.f);
        }
    }
}

extern "C" void kernel_launch(void* const* d_in, const int* in_sizes, int n_in,
                              void* d_out, int out_size) {
    const float* x1 = (const float*)d_in[0];
    const float* x2 = (const float*)d_in[1];
    const float* W1 = (const float*)d_in[2];
    const float* W2 = (const float*)d_in[3];
    const float* V  = (const float*)d_in[4];
    const float* b  = (const float*)d_in[5];
    float* out = (float*)d_out;

    prep_x<<<512, 256>>>(x1, x2);
    prep_w<<<512, 256>>>(W1, W2);
    prep_p2h<<<NN / 256, 256>>>(V, b);   // reads gXfrag: must follow prep_x

    cudaFuncSetAttribute(ntn_main,
                         cudaFuncAttributeMaxDynamicSharedMemorySize, SMEM_MAIN);
    dim3 grid(NN / 256, KK);
    ntn_main<<<grid, 256, SMEM_MAIN>>>(out);
}